// round 2
// baseline (speedup 1.0000x reference)
#include <cuda_runtime.h>

// 2-layer LSTM scan: B=1024, H=64, S=512, input dim 1, future_preds=0.
// 128 persistent CTAs x 256 threads; CTA owns 8 batch elements for all 512 steps.
// Thread r owns gate-row r. Weights pre-packed into f32x2 (u64) registers;
// dot products use packed fma.rn.f32x2 with 2 independent accumulators.
// Hidden vectors read from SMEM via ld.shared.v2.u64 (LDS.128 -> 2 paired b64).

#define HID 64
#define G4  256   // 4*H
#define BB  8     // batch elements per block
#define TPB 256
#define BATCH 1024
#define SEQ 512

typedef unsigned long long u64;

__device__ __forceinline__ u64 pack2(float lo, float hi) {
    u64 r; asm("mov.b64 %0, {%1, %2};" : "=l"(r) : "f"(lo), "f"(hi)); return r;
}
__device__ __forceinline__ void unpack2(u64 v, float& lo, float& hi) {
    asm("mov.b64 {%0, %1}, %2;" : "=f"(lo), "=f"(hi) : "l"(v));
}
__device__ __forceinline__ void ffma2(u64& d, u64 a, u64 b) {
    asm("fma.rn.f32x2 %0, %1, %2, %0;" : "+l"(d) : "l"(a), "l"(b));
}
__device__ __forceinline__ void lds_2x64(u64& a, u64& b, unsigned addr) {
    asm volatile("ld.shared.v2.u64 {%0, %1}, [%2];" : "=l"(a), "=l"(b) : "r"(addr));
}

__device__ __forceinline__ float fsigmoid(float x) {
    return __fdividef(1.0f, 1.0f + __expf(-x));
}
__device__ __forceinline__ float ftanh(float x) {
    float xx = fminf(fmaxf(x, -15.0f), 15.0f);
    float e = __expf(2.0f * xx);
    return __fdividef(e - 1.0f, e + 1.0f);
}

__global__ __launch_bounds__(TPB, 1)
void lstm_kernel(const float* __restrict__ input,
                 const float* __restrict__ W_ih1, const float* __restrict__ W_hh1,
                 const float* __restrict__ b_ih1, const float* __restrict__ b_hh1,
                 const float* __restrict__ W_ih2, const float* __restrict__ W_hh2,
                 const float* __restrict__ b_ih2, const float* __restrict__ b_hh2,
                 const float* __restrict__ W_lin, const float* __restrict__ b_lin,
                 float* __restrict__ out)
{
    __shared__ float xs[BB][SEQ];                       // staged inputs (16 KB)
    __shared__ float g1[BB][G4];                        // layer-1 gates (8 KB)
    __shared__ float g2[BB][G4];                        // layer-2 gates (8 KB)
    __shared__ __align__(16) float h1s[BB][HID];
    __shared__ __align__(16) float c1s[BB][HID];
    __shared__ __align__(16) float h2s[BB][HID];
    __shared__ __align__(16) float c2s[BB][HID];
    __shared__ float wl[HID];
    __shared__ float blin;

    const int r  = threadIdx.x;        // gate row 0..255 this thread owns
    const int b0 = blockIdx.x * BB;    // first batch element of this block

    // ---- Pack this row's weights into f32x2 register pairs (one time) ----
    u64 wA[HID/2], wB[HID/2], wC[HID/2];
    #pragma unroll
    for (int k = 0; k < HID/2; k++) {
        wA[k] = pack2(W_hh1[r*HID + 2*k], W_hh1[r*HID + 2*k + 1]);
        wB[k] = pack2(W_ih2[r*HID + 2*k], W_ih2[r*HID + 2*k + 1]);
        wC[k] = pack2(W_hh2[r*HID + 2*k], W_hh2[r*HID + 2*k + 1]);
    }
    const float bias1 = b_ih1[r] + b_hh1[r];
    const float bias2 = b_ih2[r] + b_hh2[r];
    const float wx    = W_ih1[r];      // input dim is 1

    // ---- Stage inputs + init state ----
    for (int idx = r; idx < BB * SEQ; idx += TPB)
        xs[idx / SEQ][idx % SEQ] = input[b0 * SEQ + idx];   // coalesced
    for (int idx = r; idx < BB * HID; idx += TPB) {
        int b = idx / HID, j = idx % HID;
        h1s[b][j] = 0.f; c1s[b][j] = 0.f; h2s[b][j] = 0.f; c2s[b][j] = 0.f;
    }
    if (r < HID) wl[r] = W_lin[r];
    if (r == 0)  blin  = b_lin[0];
    __syncthreads();

    const int wid = r >> 5, lane = r & 31;

    const unsigned h1a = (unsigned)__cvta_generic_to_shared(&h1s[0][0]);
    const unsigned h2a = (unsigned)__cvta_generic_to_shared(&h2s[0][0]);

    for (int t = 0; t < SEQ; t++) {
        // ---- Phase A: layer-1 gates: g1[b][r] = bias1 + wx*x + wA . h1[b] ----
        #pragma unroll 1
        for (int b = 0; b < BB; b++) {
            u64 acc0 = 0ull, acc1 = 0ull;      // (+0,+0) packed
            unsigned hp = h1a + b * (HID * 4);
            #pragma unroll
            for (int q = 0; q < HID/4; q++) {  // 16 x LDS.128
                u64 hv0, hv1;
                lds_2x64(hv0, hv1, hp + q * 16);
                ffma2(acc0, wA[2*q],     hv0);
                ffma2(acc1, wA[2*q + 1], hv1);
            }
            float a0, a1, a2, a3;
            unpack2(acc0, a0, a1); unpack2(acc1, a2, a3);
            g1[b][r] = fmaf(wx, xs[b][t], bias1) + ((a0 + a1) + (a2 + a3));
        }
        __syncthreads();

        // ---- Act1: update h1, c1 (512 tasks over 256 threads) ----
        #pragma unroll
        for (int rep = 0; rep < 2; rep++) {
            int task = r + rep * TPB;
            int b = task >> 6, j = task & 63;
            float gi = g1[b][j],           gf = g1[b][HID   + j];
            float gg = g1[b][2*HID + j],   go = g1[b][3*HID + j];
            float cn = fsigmoid(gf) * c1s[b][j] + fsigmoid(gi) * ftanh(gg);
            c1s[b][j] = cn;
            h1s[b][j] = fsigmoid(go) * ftanh(cn);
        }
        __syncthreads();

        // ---- Phase B: layer-2 gates: g2[b][r] = bias2 + wB . h1[b] + wC . h2[b] ----
        #pragma unroll 1
        for (int b = 0; b < BB; b++) {
            u64 acc0 = 0ull, acc1 = 0ull, acc2 = 0ull, acc3 = 0ull;
            unsigned hp1 = h1a + b * (HID * 4);
            unsigned hp2 = h2a + b * (HID * 4);
            #pragma unroll
            for (int q = 0; q < HID/4; q++) {  // 32 x LDS.128
                u64 v0, v1, w0, w1;
                lds_2x64(v0, v1, hp1 + q * 16);
                lds_2x64(w0, w1, hp2 + q * 16);
                ffma2(acc0, wB[2*q],     v0);
                ffma2(acc1, wB[2*q + 1], v1);
                ffma2(acc2, wC[2*q],     w0);
                ffma2(acc3, wC[2*q + 1], w1);
            }
            float a0, a1, a2, a3, a4, a5, a6, a7;
            unpack2(acc0, a0, a1); unpack2(acc1, a2, a3);
            unpack2(acc2, a4, a5); unpack2(acc3, a6, a7);
            g2[b][r] = bias2 + (((a0 + a1) + (a2 + a3)) + ((a4 + a5) + (a6 + a7)));
        }
        __syncthreads();

        // ---- Act2: update h2, c2 ----
        #pragma unroll
        for (int rep = 0; rep < 2; rep++) {
            int task = r + rep * TPB;
            int b = task >> 6, j = task & 63;
            float gi = g2[b][j],           gf = g2[b][HID   + j];
            float gg = g2[b][2*HID + j],   go = g2[b][3*HID + j];
            float cn = fsigmoid(gf) * c2s[b][j] + fsigmoid(gi) * ftanh(gg);
            c2s[b][j] = cn;
            h2s[b][j] = fsigmoid(go) * ftanh(cn);
        }
        __syncthreads();

        // ---- Output: warp w reduces batch element b=w: out = wl . h2[b] + blin ----
        {
            int b = wid;
            float v = wl[lane] * h2s[b][lane] + wl[lane + 32] * h2s[b][lane + 32];
            #pragma unroll
            for (int off = 16; off; off >>= 1)
                v += __shfl_down_sync(0xFFFFFFFFu, v, off);
            if (lane == 0) out[(b0 + b) * SEQ + t] = v + blin;
        }
        // No barrier needed before next Phase A:
        //  - next writes touch g1 (last read before sync2 this step)
        //  - h2 (read here) is next written only after 3 more barriers (next Act2)
    }
}

extern "C" void kernel_launch(void* const* d_in, const int* in_sizes, int n_in,
                              void* d_out, int out_size) {
    (void)in_sizes; (void)n_in; (void)out_size;
    const float* input = (const float*)d_in[0];
    const float* W_ih1 = (const float*)d_in[1];
    const float* W_hh1 = (const float*)d_in[2];
    const float* b_ih1 = (const float*)d_in[3];
    const float* b_hh1 = (const float*)d_in[4];
    const float* W_ih2 = (const float*)d_in[5];
    const float* W_hh2 = (const float*)d_in[6];
    const float* b_ih2 = (const float*)d_in[7];
    const float* b_hh2 = (const float*)d_in[8];
    const float* W_lin = (const float*)d_in[9];
    const float* b_lin = (const float*)d_in[10];
    float* out = (float*)d_out;

    lstm_kernel<<<BATCH / BB, TPB>>>(input, W_ih1, W_hh1, b_ih1, b_hh1,
                                     W_ih2, W_hh2, b_ih2, b_hh2,
                                     W_lin, b_lin, out);
}

// round 3
// speedup vs baseline: 1.5250x; 1.5250x over previous
#include <cuda_runtime.h>

// 2-layer LSTM scan: B=1024, H=64, S=512, input dim 1, future_preds=0.
// 128 persistent CTAs x 512 threads (4 warps/SMSP for latency coverage).
// Split-K: thread (s = tid>>8, r = tid&255) owns HALF of gate-row r:
//   wA = W_hh1[r][32s:32s+32], wB = W_ih2[r][...], wC = W_hh2[r][...]
// (96 weight registers/thread; fits 128-reg budget at 512 threads/SM).
// Each half writes a partial gate to SMEM p[s][b][r]; activation phase sums.

#define HID 64
#define HALF 32   // k-elements per thread
#define G4  256   // 4*H
#define BB  8     // batch elements per block
#define TPB 512
#define BATCH 1024
#define SEQ 512

__device__ __forceinline__ float fsigmoid(float x) {
    return __fdividef(1.0f, 1.0f + __expf(-x));
}
__device__ __forceinline__ float ftanh(float x) {
    float xx = fminf(fmaxf(x, -15.0f), 15.0f);
    float e = __expf(2.0f * xx);
    return __fdividef(e - 1.0f, e + 1.0f);
}

__global__ __launch_bounds__(TPB, 1)
void lstm_kernel(const float* __restrict__ input,
                 const float* __restrict__ W_ih1, const float* __restrict__ W_hh1,
                 const float* __restrict__ b_ih1, const float* __restrict__ b_hh1,
                 const float* __restrict__ W_ih2, const float* __restrict__ W_hh2,
                 const float* __restrict__ b_ih2, const float* __restrict__ b_hh2,
                 const float* __restrict__ W_lin, const float* __restrict__ b_lin,
                 float* __restrict__ out)
{
    __shared__ float xs[BB][SEQ];                       // staged inputs (16 KB)
    __shared__ float p[2][BB][G4];                      // partial gates (16 KB)
    __shared__ __align__(16) float h1s[BB][HID];
    __shared__ __align__(16) float c1s[BB][HID];
    __shared__ __align__(16) float h2s[BB][HID];
    __shared__ __align__(16) float c2s[BB][HID];
    __shared__ float wl[HID];
    __shared__ float blin;

    const int tid = threadIdx.x;
    const int s   = tid >> 8;          // k-half: 0 or 1 (warp-uniform)
    const int r   = tid & 255;         // gate row 0..255
    const int b0  = blockIdx.x * BB;   // first batch element of this block
    const int kofs = s * HALF;

    // ---- Load this half-row's weights into registers (one time) ----
    float wA[HALF], wB[HALF], wC[HALF];
    #pragma unroll
    for (int k = 0; k < HALF; k++) {
        wA[k] = W_hh1[r * HID + kofs + k];
        wB[k] = W_ih2[r * HID + kofs + k];
        wC[k] = W_hh2[r * HID + kofs + k];
    }
    // s==0 thread carries bias + input term; s==1 carries pure partial
    const float bias1 = (s == 0) ? (b_ih1[r] + b_hh1[r]) : 0.0f;
    const float bias2 = (s == 0) ? (b_ih2[r] + b_hh2[r]) : 0.0f;
    const float wx    = (s == 0) ? W_ih1[r] : 0.0f;

    // ---- Stage inputs + init state ----
    for (int idx = tid; idx < BB * SEQ; idx += TPB)
        xs[idx / SEQ][idx % SEQ] = input[b0 * SEQ + idx];   // coalesced
    if (tid < BB * HID) {
        int b = tid / HID, j = tid % HID;
        h1s[b][j] = 0.f; c1s[b][j] = 0.f; h2s[b][j] = 0.f; c2s[b][j] = 0.f;
    }
    if (tid < HID) wl[tid] = W_lin[tid];
    if (tid == 0)  blin  = b_lin[0];
    __syncthreads();

    const int wid = tid >> 5, lane = tid & 31;
    const int ab = tid >> 6;          // act-phase batch 0..7
    const int aj = tid & 63;          // act-phase hidden index

    for (int t = 0; t < SEQ; t++) {
        // ---- Phase A: partial layer-1 gates over k in [kofs, kofs+32) ----
        #pragma unroll 2
        for (int b = 0; b < BB; b++) {
            float acc0 = fmaf(wx, xs[b][t], bias1);
            float acc1 = 0.0f;
            const float4* hp = (const float4*)&h1s[b][kofs];
            #pragma unroll
            for (int q = 0; q < HALF / 4; q++) {
                float4 hv = hp[q];
                acc0 = fmaf(wA[4*q+0], hv.x, acc0);
                acc1 = fmaf(wA[4*q+1], hv.y, acc1);
                acc0 = fmaf(wA[4*q+2], hv.z, acc0);
                acc1 = fmaf(wA[4*q+3], hv.w, acc1);
            }
            p[s][b][r] = acc0 + acc1;
        }
        __syncthreads();

        // ---- Act1: one task per thread: (b=ab, j=aj) ----
        {
            float gi = p[0][ab][aj]         + p[1][ab][aj];
            float gf = p[0][ab][HID + aj]   + p[1][ab][HID + aj];
            float gg = p[0][ab][2*HID + aj] + p[1][ab][2*HID + aj];
            float go = p[0][ab][3*HID + aj] + p[1][ab][3*HID + aj];
            float cn = fsigmoid(gf) * c1s[ab][aj] + fsigmoid(gi) * ftanh(gg);
            c1s[ab][aj] = cn;
            h1s[ab][aj] = fsigmoid(go) * ftanh(cn);
        }
        __syncthreads();

        // ---- Phase B: partial layer-2 gates: wB . h1 + wC . h2 (half-k) ----
        #pragma unroll 2
        for (int b = 0; b < BB; b++) {
            float acc0 = bias2, acc1 = 0.0f, acc2 = 0.0f, acc3 = 0.0f;
            const float4* hp1 = (const float4*)&h1s[b][kofs];
            const float4* hp2 = (const float4*)&h2s[b][kofs];
            #pragma unroll
            for (int q = 0; q < HALF / 4; q++) {
                float4 v1 = hp1[q];
                float4 v2 = hp2[q];
                acc0 = fmaf(wB[4*q+0], v1.x, acc0);
                acc1 = fmaf(wB[4*q+1], v1.y, acc1);
                acc0 = fmaf(wB[4*q+2], v1.z, acc0);
                acc1 = fmaf(wB[4*q+3], v1.w, acc1);
                acc2 = fmaf(wC[4*q+0], v2.x, acc2);
                acc3 = fmaf(wC[4*q+1], v2.y, acc3);
                acc2 = fmaf(wC[4*q+2], v2.z, acc2);
                acc3 = fmaf(wC[4*q+3], v2.w, acc3);
            }
            p[s][b][r] = (acc0 + acc1) + (acc2 + acc3);
        }
        __syncthreads();

        // ---- Act2: one task per thread ----
        {
            float gi = p[0][ab][aj]         + p[1][ab][aj];
            float gf = p[0][ab][HID + aj]   + p[1][ab][HID + aj];
            float gg = p[0][ab][2*HID + aj] + p[1][ab][2*HID + aj];
            float go = p[0][ab][3*HID + aj] + p[1][ab][3*HID + aj];
            float cn = fsigmoid(gf) * c2s[ab][aj] + fsigmoid(gi) * ftanh(gg);
            c2s[ab][aj] = cn;
            h2s[ab][aj] = fsigmoid(go) * ftanh(cn);
        }
        __syncthreads();

        // ---- Output: warp w < 8 reduces batch element b=w ----
        if (wid < BB) {
            int b = wid;
            float v = wl[lane] * h2s[b][lane] + wl[lane + 32] * h2s[b][lane + 32];
            #pragma unroll
            for (int off = 16; off; off >>= 1)
                v += __shfl_down_sync(0xFFFFFFFFu, v, off);
            if (lane == 0) out[(b0 + b) * SEQ + t] = v + blin;
        }
        // No barrier needed before next Phase A: next writes touch p (last
        // read before the act2 barrier), and h2s (read here) is next written
        // only after 3 more barriers (next step's Act2).
    }
}

extern "C" void kernel_launch(void* const* d_in, const int* in_sizes, int n_in,
                              void* d_out, int out_size) {
    (void)in_sizes; (void)n_in; (void)out_size;
    const float* input = (const float*)d_in[0];
    const float* W_ih1 = (const float*)d_in[1];
    const float* W_hh1 = (const float*)d_in[2];
    const float* b_ih1 = (const float*)d_in[3];
    const float* b_hh1 = (const float*)d_in[4];
    const float* W_ih2 = (const float*)d_in[5];
    const float* W_hh2 = (const float*)d_in[6];
    const float* b_ih2 = (const float*)d_in[7];
    const float* b_hh2 = (const float*)d_in[8];
    const float* W_lin = (const float*)d_in[9];
    const float* b_lin = (const float*)d_in[10];
    float* out = (float*)d_out;

    lstm_kernel<<<BATCH / BB, TPB>>>(input, W_ih1, W_hh1, b_ih1, b_hh1,
                                     W_ih2, W_hh2, b_ih2, b_hh2,
                                     W_lin, b_lin, out);
}

// round 5
// speedup vs baseline: 4.6030x; 3.0183x over previous
#include <cuda_runtime.h>
#include <cuda_bf16.h>
#include <cstdint>

// 2-layer LSTM scan, B=1024, H=64, S=512, via warp-level HMMA (mma.sync bf16,
// fp32 accum) with split-precision (hi/lo bf16, 3 passes).
// 128 CTAs x 512 threads (16 warps); CTA owns NB=8 batch columns.
// Warp w owns gate rows [16w,16w+16). Weight A-fragments persistent in regs:
//   L1: W_hh1 (K=64)  -> 32 regs ; L2: [W_ih2|W_hh2] (K=128) -> 64 regs.
// h-state in SMEM as bf16 hi/lo, stride 68 words (conflict-free B-frag LDS).
// Activations fp32 __expf (proven rel_err ~9e-7 path), c-state in registers.

#define HID 64
#define NB  8
#define TPB 512
#define BATCH 1024
#define SEQ 512
#define NCTA (BATCH/NB)      // 128
#define HSW 68               // hs row stride in words (k pairs 0..63 + pad 4)
#define GSTR 264             // gate buffer row stride (floats)

__device__ __forceinline__ uint32_t packbf(float a, float b) {
    __nv_bfloat162 v = __floats2bfloat162_rn(a, b);   // .x = a (low half)
    return *(uint32_t*)&v;
}
__device__ __forceinline__ void mma16816(float* d, const uint32_t* a,
                                         uint32_t b0, uint32_t b1) {
    asm("mma.sync.aligned.m16n8k16.row.col.f32.bf16.bf16.f32 "
        "{%0,%1,%2,%3}, {%4,%5,%6,%7}, {%8,%9}, {%0,%1,%2,%3};"
        : "+f"(d[0]), "+f"(d[1]), "+f"(d[2]), "+f"(d[3])
        : "r"(a[0]), "r"(a[1]), "r"(a[2]), "r"(a[3]), "r"(b0), "r"(b1));
}
__device__ __forceinline__ float fsigmoid(float x) {
    return __fdividef(1.0f, 1.0f + __expf(-x));
}
__device__ __forceinline__ float ftanh(float x) {
    float xx = fminf(fmaxf(x, -15.0f), 15.0f);
    float e = __expf(2.0f * xx);
    return __fdividef(e - 1.0f, e + 1.0f);
}

__global__ __launch_bounds__(TPB, 1)
void lstm_kernel(const float* __restrict__ input,
                 const float* __restrict__ W_ih1, const float* __restrict__ W_hh1,
                 const float* __restrict__ b_ih1, const float* __restrict__ b_hh1,
                 const float* __restrict__ W_ih2, const float* __restrict__ W_hh2,
                 const float* __restrict__ b_ih2, const float* __restrict__ b_hh2,
                 const float* __restrict__ W_lin, const float* __restrict__ b_lin,
                 float* __restrict__ out)
{
    // hs[p][n][word]: bf16 pair per word; k=0..63 = h1, k=64..127 = h2.
    __shared__ uint32_t hs[2][NB][HSW];
    __shared__ float g1sh[NB][GSTR];     // layer-1 gates [batch][256 rows]
    __shared__ float g2sh[NB][GSTR];     // layer-2 gates
    __shared__ float wxs[256], b1s[256], b2s[256], wls[HID];
    __shared__ float reds[16];
    __shared__ float blin;

    const int tid  = threadIdx.x;
    const int w    = tid >> 5, lane = tid & 31;
    const int g    = lane >> 2, t = lane & 3;   // mma group / thread-in-group
    const int R    = 16 * w + g;                // this thread's low gate row
    const int b0   = blockIdx.x * NB;
    const int ab   = tid >> 6;                  // act-phase batch (0..7)
    const int aj   = tid & 63;                  // act-phase hidden index

    // ---- Persistent A-fragments (hi/lo bf16), loaded once from gmem ----
    uint32_t wa1[2][4][4];                      // [prec][kt][reg]
    uint32_t wa2[2][8][4];
    #pragma unroll
    for (int kt = 0; kt < 4; kt++) {
        #pragma unroll
        for (int r = 0; r < 4; r++) {
            int row = R + ((r & 1) ? 8 : 0);
            int cb  = kt * 16 + ((r >= 2) ? 8 : 0) + 2 * t;
            float v0 = W_hh1[row * HID + cb], v1 = W_hh1[row * HID + cb + 1];
            float h0 = __bfloat162float(__float2bfloat16(v0));
            float h1 = __bfloat162float(__float2bfloat16(v1));
            wa1[0][kt][r] = packbf(h0, h1);
            wa1[1][kt][r] = packbf(v0 - h0, v1 - h1);
        }
    }
    #pragma unroll
    for (int kt = 0; kt < 8; kt++) {
        #pragma unroll
        for (int r = 0; r < 4; r++) {
            int row = R + ((r & 1) ? 8 : 0);
            int cb  = kt * 16 + ((r >= 2) ? 8 : 0) + 2 * t;
            float v0 = (cb < 64) ? W_ih2[row * HID + cb]
                                 : W_hh2[row * HID + cb - 64];
            float v1 = (cb + 1 < 64) ? W_ih2[row * HID + cb + 1]
                                     : W_hh2[row * HID + cb + 1 - 64];
            float h0 = __bfloat162float(__float2bfloat16(v0));
            float h1 = __bfloat162float(__float2bfloat16(v1));
            wa2[0][kt][r] = packbf(h0, h1);
            wa2[1][kt][r] = packbf(v0 - h0, v1 - h1);
        }
    }

    // ---- Init SMEM ----
    for (int i = tid; i < 2 * NB * HSW; i += TPB) ((uint32_t*)hs)[i] = 0;
    for (int i = tid; i < 256; i += TPB) {
        wxs[i] = W_ih1[i];
        b1s[i] = b_ih1[i] + b_hh1[i];
        b2s[i] = b_ih2[i] + b_hh2[i];
    }
    if (tid < HID) wls[tid] = W_lin[tid];
    if (tid == 0) blin = b_lin[0];
    __syncthreads();

    float c1 = 0.f, c2 = 0.f;

    for (int t_step = 0; t_step < SEQ; t_step++) {
        const float xval = input[(b0 + ab) * SEQ + t_step];  // prefetch

        // ===== Layer 1 MMA: gates[256x8] = W_hh1 @ h1, 3 passes =====
        {
            float d[4] = {0.f, 0.f, 0.f, 0.f};
            float e[4] = {0.f, 0.f, 0.f, 0.f};
            #pragma unroll
            for (int kt = 0; kt < 4; kt++) {
                uint32_t bh0 = hs[0][g][kt * 8 + t];
                uint32_t bh1 = hs[0][g][kt * 8 + 4 + t];
                uint32_t bl0 = hs[1][g][kt * 8 + t];
                uint32_t bl1 = hs[1][g][kt * 8 + 4 + t];
                mma16816(d, wa1[0][kt], bh0, bh1);
                mma16816(e, wa1[1][kt], bh0, bh1);
                mma16816(e, wa1[0][kt], bl0, bl1);
            }
            g1sh[2 * t    ][R    ] = d[0] + e[0];
            g1sh[2 * t + 1][R    ] = d[1] + e[1];
            g1sh[2 * t    ][R + 8] = d[2] + e[2];
            g1sh[2 * t + 1][R + 8] = d[3] + e[3];
        }
        __syncthreads();

        // ===== Act1: (b=ab, j=aj); write h1 bf16 hi/lo =====
        {
            float gI = g1sh[ab][aj]       + fmaf(wxs[aj],       xval, b1s[aj]);
            float gF = g1sh[ab][64 + aj]  + fmaf(wxs[64 + aj],  xval, b1s[64 + aj]);
            float gG = g1sh[ab][128 + aj] + fmaf(wxs[128 + aj], xval, b1s[128 + aj]);
            float gO = g1sh[ab][192 + aj] + fmaf(wxs[192 + aj], xval, b1s[192 + aj]);
            float cn = fsigmoid(gF) * c1 + fsigmoid(gI) * ftanh(gG);
            c1 = cn;
            float h = fsigmoid(gO) * ftanh(cn);
            __nv_bfloat16 hi = __float2bfloat16(h);
            ((__nv_bfloat16*)&hs[0][ab][0])[aj] = hi;
            ((__nv_bfloat16*)&hs[1][ab][0])[aj] =
                __float2bfloat16(h - __bfloat162float(hi));
        }
        __syncthreads();

        // ===== Layer 2 MMA: gates = [W_ih2|W_hh2] @ [h1;h2], 3 passes =====
        {
            float d[4] = {0.f, 0.f, 0.f, 0.f};
            float e[4] = {0.f, 0.f, 0.f, 0.f};
            #pragma unroll
            for (int kt = 0; kt < 8; kt++) {
                uint32_t bh0 = hs[0][g][kt * 8 + t];
                uint32_t bh1 = hs[0][g][kt * 8 + 4 + t];
                uint32_t bl0 = hs[1][g][kt * 8 + t];
                uint32_t bl1 = hs[1][g][kt * 8 + 4 + t];
                mma16816(d, wa2[0][kt], bh0, bh1);
                mma16816(e, wa2[1][kt], bh0, bh1);
                mma16816(e, wa2[0][kt], bl0, bl1);
            }
            g2sh[2 * t    ][R    ] = d[0] + e[0];
            g2sh[2 * t + 1][R    ] = d[1] + e[1];
            g2sh[2 * t    ][R + 8] = d[2] + e[2];
            g2sh[2 * t + 1][R + 8] = d[3] + e[3];
        }
        __syncthreads();

        // ===== Act2 + output partial =====
        {
            float gI = g2sh[ab][aj]       + b2s[aj];
            float gF = g2sh[ab][64 + aj]  + b2s[64 + aj];
            float gG = g2sh[ab][128 + aj] + b2s[128 + aj];
            float gO = g2sh[ab][192 + aj] + b2s[192 + aj];
            float cn = fsigmoid(gF) * c2 + fsigmoid(gI) * ftanh(gG);
            c2 = cn;
            float h = fsigmoid(gO) * ftanh(cn);
            __nv_bfloat16 hi = __float2bfloat16(h);
            ((__nv_bfloat16*)&hs[0][ab][0])[64 + aj] = hi;
            ((__nv_bfloat16*)&hs[1][ab][0])[64 + aj] =
                __float2bfloat16(h - __bfloat162float(hi));
            float vout = wls[aj] * h;
            #pragma unroll
            for (int off = 16; off; off >>= 1)
                vout += __shfl_down_sync(0xFFFFFFFFu, vout, off);
            if (lane == 0) reds[w] = vout;   // warp w: batch w>>1, half (w&1)
        }
        __syncthreads();

        if (tid < NB)
            out[(b0 + tid) * SEQ + t_step] = reds[2 * tid] + reds[2 * tid + 1] + blin;
        // No extra barrier: next phase writes g1sh (last read before the
        // act1 barrier) and reads hs (written before the barriers above);
        // reds is next written only after 3 more barriers.
    }
}

extern "C" void kernel_launch(void* const* d_in, const int* in_sizes, int n_in,
                              void* d_out, int out_size) {
    (void)in_sizes; (void)n_in; (void)out_size;
    const float* input = (const float*)d_in[0];
    const float* W_ih1 = (const float*)d_in[1];
    const float* W_hh1 = (const float*)d_in[2];
    const float* b_ih1 = (const float*)d_in[3];
    const float* b_hh1 = (const float*)d_in[4];
    const float* W_ih2 = (const float*)d_in[5];
    const float* W_hh2 = (const float*)d_in[6];
    const float* b_ih2 = (const float*)d_in[7];
    const float* b_hh2 = (const float*)d_in[8];
    const float* W_lin = (const float*)d_in[9];
    const float* b_lin = (const float*)d_in[10];
    float* out = (float*)d_out;

    lstm_kernel<<<NCTA, TPB>>>(input, W_ih1, W_hh1, b_ih1, b_hh1,
                               W_ih2, W_hh2, b_ih2, b_hh2,
                               W_lin, b_lin, out);
}